// round 14
// baseline (speedup 1.0000x reference)
#include <cuda_runtime.h>
#include <cuda_fp16.h>
#include <cstdint>
#include <cstddef>

#define EPS   1e-6f
#define B_    16
#define NN    1024
#define FDIM  64
#define OUTD  128
#define KC    32
#define NITER (NN / KC)
#define MROWS 64                       // rows per CTA

// strides in b32 units
#define SA_STRH 20                     // 64B data + 16B pad per k-tile row
#define OC_STRH 100
#define KM_STRH 100

// smem layout (bytes)
#define OFF_ADIAG 0                    // 64 floats
#define OFF_INV   256
#define OFF_SROW  512
#define OFF_DYN   1024
#define ASTG_B    (MROWS * SA_STRH * 4)            // 5120
#define BSTG_B    (128 * SA_STRH * 4)              // 10240
#define STG_B     (ASTG_B + BSTG_B)                // 15360
#define OFF_STAGE(s) (OFF_DYN + (s) * STG_B)       // 3 stages -> ends 47104
#define OFF_OC    OFF_DYN                          // 64*400 = 25600 (inside stages)
#define OFF_KM    (OFF_DYN + 3 * STG_B)            // 47104
#define SMEM_BYTES (OFF_KM + 128 * KM_STRH * 4)    // 98304 (96 KB)

__device__ float  g_inv[B_ * NN];
__device__ float  g_s[B_ * NN];
__device__ __half g_Ah[(size_t)B_ * NN * NN];
__device__ __half g_Bh[(size_t)B_ * 128 * NN];

__device__ __forceinline__ uint32_t smem_u32(const void* p) {
    uint32_t a;
    asm("{ .reg .u64 t; cvta.to.shared.u64 t, %1; cvt.u32.u64 %0, t; }"
        : "=r"(a) : "l"(p));
    return a;
}
__device__ __forceinline__ void cp_async16(uint32_t saddr, const void* g) {
    asm volatile("cp.async.cg.shared.global [%0], [%1], 16;"
                 :: "r"(saddr), "l"(g) : "memory");
}
#define CP_COMMIT() asm volatile("cp.async.commit_group;" ::: "memory")
#define CP_WAIT1()  asm volatile("cp.async.wait_group 1;" ::: "memory")
__device__ __forceinline__ uint32_t h2pack(float lo, float hi) {
    __half2 h = __floats2half2_rn(lo, hi);
    return *(uint32_t*)&h;
}
__device__ __forceinline__ float h2f_rn(float v) {
    return __half2float(__float2half_rn(v));
}
__device__ __forceinline__ void mma_f16(float* c, const uint32_t* a, const uint32_t* b) {
    asm volatile(
        "mma.sync.aligned.m16n8k16.row.col.f32.f16.f16.f32 "
        "{%0,%1,%2,%3}, {%4,%5,%6,%7}, {%8,%9}, {%0,%1,%2,%3};"
        : "+f"(c[0]), "+f"(c[1]), "+f"(c[2]), "+f"(c[3])
        : "r"(a[0]), "r"(a[1]), "r"(a[2]), "r"(a[3]), "r"(b[0]), "r"(b[1]));
}

// ---------------------------------------------------------------------------
// Kernel 1: deg + fp16-A conversion (row already in registers).
// ---------------------------------------------------------------------------
__global__ void deg_prep_kernel(const float* __restrict__ A) {
    int warp = (blockIdx.x * blockDim.x + threadIdx.x) >> 5;
    int lane = threadIdx.x & 31;
    if (warp >= B_ * NN) return;
    const float* row = A + (size_t)warp * NN;
    const float4* r4 = (const float4*)row;
    float4 v[8];
    float sum = 0.f;
#pragma unroll
    for (int w = 0; w < 8; w++) {
        v[w] = r4[w * 32 + lane];
        sum += v[w].x + v[w].y + v[w].z + v[w].w;
    }
#pragma unroll
    for (int off = 16; off > 0; off >>= 1)
        sum += __shfl_down_sync(0xFFFFFFFFu, sum, off);
    if (lane == 0) {
        float deg = sum - row[warp % NN] + 1.0f;
        g_inv[warp] = 1.0f / (EPS + deg);
        g_s[warp]   = 1.0f / (EPS + sqrtf(deg));
    }
    uint2* dst = (uint2*)(g_Ah + (size_t)warp * NN);
#pragma unroll
    for (int w = 0; w < 8; w++) {
        uint2 h;
        h.x = h2pack(v[w].x, v[w].y);
        h.y = h2pack(v[w].z, v[w].w);
        dst[w * 32 + lane] = h;
    }
}

// ---------------------------------------------------------------------------
// Kernel 2: x -> g_Bh[b][f][k] fp16, f-major (f>=64 holds s*x)
// ---------------------------------------------------------------------------
__global__ __launch_bounds__(256, 4)
void prep_kernel(const float* __restrict__ x) {
    __shared__ float xt[128][65];
    __shared__ float sk[128];
    const int b = blockIdx.y, k0 = blockIdx.x * 128;
    const int tid = threadIdx.x;
    const float* xb = x + ((size_t)b * NN + k0) * FDIM;
#pragma unroll
    for (int q = 0; q < 8; q++) {
        int e = tid + q * 256;
        int row = e >> 4, c4 = (e & 15) * 4;
        float4 v = *(const float4*)&xb[(size_t)row * FDIM + c4];
        xt[row][c4] = v.x; xt[row][c4 + 1] = v.y;
        xt[row][c4 + 2] = v.z; xt[row][c4 + 3] = v.w;
    }
    if (tid < 128) sk[tid] = g_s[b * NN + k0 + tid];
    __syncthreads();
    uint32_t* dst = (uint32_t*)(g_Bh + (size_t)b * 128 * NN + k0);
#pragma unroll
    for (int q = 0; q < 32; q++) {
        int e = tid + q * 256;
        int f = e >> 6, kp = e & 63;
        float v0, v1;
        if (f < 64) {
            v0 = xt[2 * kp][f];
            v1 = xt[2 * kp + 1][f];
        } else {
            v0 = sk[2 * kp] * xt[2 * kp][f - 64];
            v1 = sk[2 * kp + 1] * xt[2 * kp + 1][f - 64];
        }
        dst[(size_t)f * (NN / 2) + kp] = h2pack(v0, v1);
    }
}

// ---------------------------------------------------------------------------
// Kernel 3: fused fp16 GEMMs. 256 threads / 64 rows per CTA, 2 CTAs/SM.
// 3-stage cp.async pipeline, zero LDG/cvt/STS in the mainloop.
// ---------------------------------------------------------------------------
__global__ __launch_bounds__(256, 2)
void fused_mma_kernel(const float* __restrict__ A, const float* __restrict__ x,
                      const float* __restrict__ Kmat, const float* __restrict__ bias,
                      float* __restrict__ out) {
    extern __shared__ char smc[];
    float* smf = (float*)smc;
    const uint32_t sb = smem_u32(smc);
    const int tid  = threadIdx.x;
    const int wid  = tid >> 5;              // 0..7
    const int lane = tid & 31;
    const int b    = blockIdx.y;
    const int row0 = blockIdx.x * MROWS;
    const int lr = lane >> 2;
    const int lc = lane & 3;

    const float* Ab = A + (size_t)b * NN * NN;
    const float* xb = x + (size_t)b * NN * FDIM;

    // warp tile: rows mm..mm+31 (mm in {0,32}), cols n4..n4+31
    const int mm = (wid >> 2) * 32;
    const int n4 = (wid & 3) * 32;
    const bool scaled = (n4 >= 64);
    const int f_base = scaled ? n4 - 64 : n4;

    // ---- cp.async geometry (per stage: A 256 chunks x1/thread, B 512 x2)
    const int arow = tid >> 2;              // 0..63
    const int ach  = tid & 3;               // 16B chunk in 64B row
    const __half* gA = g_Ah + (size_t)b * NN * NN + (size_t)(row0 + arow) * NN + ach * 8;
    const __half* gB0 = g_Bh + (size_t)b * 128 * NN;
    uint32_t sAaddr[3], sBaddr[3][2];
#pragma unroll
    for (int s = 0; s < 3; s++) {
        sAaddr[s] = sb + OFF_STAGE(s) + arow * 80 + ach * 16;
#pragma unroll
        for (int q = 0; q < 2; q++) {
            int e = tid + q * 256;
            int brow = e >> 2, bch = e & 3;
            sBaddr[s][q] = sb + OFF_STAGE(s) + ASTG_B + brow * 80 + bch * 16;
        }
    }
    const __half* gBp[2];
#pragma unroll
    for (int q = 0; q < 2; q++) {
        int e = tid + q * 256;
        int brow = e >> 2, bch = e & 3;
        gBp[q] = gB0 + (size_t)brow * NN + bch * 8;
    }

    // ---- prologue: issue stages 0,1
#pragma unroll
    for (int st = 0; st < 2; st++) {
        cp_async16(sAaddr[st], gA + st * KC);
        cp_async16(sBaddr[st][0], gBp[0] + st * KC);
        cp_async16(sBaddr[st][1], gBp[1] + st * KC);
        CP_COMMIT();
    }

    // ---- scalars + KmatT fp16 (overlaps in-flight cp.async)
    if (tid < MROWS) {
        int grow = row0 + tid;
        smf[(OFF_ADIAG >> 2) + tid] = h2f_rn(__ldg(&Ab[(size_t)grow * NN + grow]));
        smf[(OFF_INV >> 2) + tid]   = g_inv[b * NN + grow];
        smf[(OFF_SROW >> 2) + tid]  = g_s[b * NN + grow];
    }
    {
        uint32_t* km = (uint32_t*)(smc + OFF_KM);
#pragma unroll 1
        for (int e = tid; e < 128 * 96; e += 256) {
            int n = e / 96;
            int kp = e - n * 96;
            float v0 = __ldg(&Kmat[(size_t)(2 * kp) * 128 + n]);
            float v1 = __ldg(&Kmat[(size_t)(2 * kp + 1) * 128 + n]);
            km[n * KM_STRH + kp] = h2pack(v0, v1);
        }
    }

    float acc[2][4][4];
#pragma unroll
    for (int mt = 0; mt < 2; mt++)
#pragma unroll
        for (int nt = 0; nt < 4; nt++)
#pragma unroll
            for (int q = 0; q < 4; q++) acc[mt][nt][q] = 0.f;

    // ---- mainloop: 32 iters; one commit/iter keeps group count uniform
    for (int it = 0; it < NITER; ++it) {
        CP_WAIT1();
        __syncthreads();
        if (it + 2 < NITER) {
            const int st = (it + 2) % 3;
            cp_async16(sAaddr[st], gA + (it + 2) * KC);
            cp_async16(sBaddr[st][0], gBp[0] + (it + 2) * KC);
            cp_async16(sBaddr[st][1], gBp[1] + (it + 2) * KC);
        }
        CP_COMMIT();
        const uint32_t* sA = (const uint32_t*)(smc + OFF_STAGE(it % 3));
        const uint32_t* sB = sA + (ASTG_B >> 2);
#pragma unroll
        for (int ks = 0; ks < 2; ks++) {
            const int kb = ks * 8;
            uint32_t af[2][4], bf2[4][2];
#pragma unroll
            for (int mt = 0; mt < 2; mt++) {
                const uint32_t* p = sA + (mm + mt * 16 + lr) * SA_STRH + kb + lc;
                af[mt][0] = p[0];
                af[mt][1] = p[8 * SA_STRH];
                af[mt][2] = p[4];
                af[mt][3] = p[8 * SA_STRH + 4];
            }
#pragma unroll
            for (int nt = 0; nt < 4; nt++) {
                const uint32_t* p = sB + (n4 + nt * 8 + lr) * SA_STRH + kb + lc;
                bf2[nt][0] = p[0];
                bf2[nt][1] = p[4];
            }
#pragma unroll
            for (int mt = 0; mt < 2; mt++)
#pragma unroll
                for (int nt = 0; nt < 4; nt++)
                    mma_f16(acc[mt][nt], af[mt], bf2[nt]);
        }
    }
    __syncthreads();

    // ---- epilogue 1: analytic diagonal fix -> ocat fp16 [64][192]
    {
        uint32_t* oc = (uint32_t*)(smc + OFF_OC);
#pragma unroll
        for (int mt = 0; mt < 2; mt++) {
#pragma unroll
            for (int nt = 0; nt < 4; nt++) {
                const int f = f_base + nt * 8 + lc * 2;
#pragma unroll
                for (int h = 0; h < 2; h++) {
                    const int r = mm + mt * 16 + lr + h * 8;
                    const float ad = smf[(OFF_ADIAG >> 2) + r];
                    const float c0 = acc[mt][nt][h * 2 + 0];
                    const float c1 = acc[mt][nt][h * 2 + 1];
                    float2 xv = *(const float2*)&xb[(size_t)(row0 + r) * FDIM + f];
                    if (!scaled) {
                        const float inv = smf[(OFF_INV >> 2) + r];
                        float xhx = h2f_rn(xv.x), xhy = h2f_rn(xv.y);
                        float o1a = c0 - ad * xhx;
                        float o1b = c1 - ad * xhy;
                        oc[r * OC_STRH + (f >> 1)] = h2pack(o1a, o1b);
                        oc[r * OC_STRH + ((64 + f) >> 1)] =
                            h2pack(inv * (o1a + xv.x), inv * (o1b + xv.y));
                    } else {
                        const float sv = smf[(OFF_SROW >> 2) + r];
                        float sxx = h2f_rn(sv * xv.x), sxy = h2f_rn(sv * xv.y);
                        float o3a = sv * c0 - sv * ad * sxx + sv * sv * xv.x;
                        float o3b = sv * c1 - sv * ad * sxy + sv * sv * xv.y;
                        oc[r * OC_STRH + ((128 + f) >> 1)] = h2pack(o3a, o3b);
                    }
                }
            }
        }
    }
    __syncthreads();

    // ---- GEMM2: out[64,128] = ocat[64,192] @ KmatT^T  (fp16, 12 k-steps)
    const uint32_t* ocp = (const uint32_t*)(smc + OFF_OC);
    const uint32_t* kmp = (const uint32_t*)(smc + OFF_KM);
    float acc2[2][4][4];
#pragma unroll
    for (int mt = 0; mt < 2; mt++)
#pragma unroll
        for (int nt = 0; nt < 4; nt++)
#pragma unroll
            for (int q = 0; q < 4; q++) acc2[mt][nt][q] = 0.f;

#pragma unroll
    for (int ks = 0; ks < 12; ks++) {
        const int kb = ks * 8;
        uint32_t af[2][4], bf2[4][2];
#pragma unroll
        for (int mt = 0; mt < 2; mt++) {
            const uint32_t* p = ocp + (mm + mt * 16 + lr) * OC_STRH + kb + lc;
            af[mt][0] = p[0];
            af[mt][1] = p[8 * OC_STRH];
            af[mt][2] = p[4];
            af[mt][3] = p[8 * OC_STRH + 4];
        }
#pragma unroll
        for (int nt = 0; nt < 4; nt++) {
            const uint32_t* p = kmp + (n4 + nt * 8 + lr) * KM_STRH + kb + lc;
            bf2[nt][0] = p[0];
            bf2[nt][1] = p[4];
        }
#pragma unroll
        for (int mt = 0; mt < 2; mt++)
#pragma unroll
            for (int nt = 0; nt < 4; nt++)
                mma_f16(acc2[mt][nt], af[mt], bf2[nt]);
    }

    // ---- bias + relu + store
#pragma unroll
    for (int mt = 0; mt < 2; mt++) {
#pragma unroll
        for (int nt = 0; nt < 4; nt++) {
            const int col = n4 + nt * 8 + lc * 2;
            float2 bv = *(const float2*)&bias[col];
#pragma unroll
            for (int h = 0; h < 2; h++) {
                const int r = mm + mt * 16 + lr + h * 8;
                float2 o;
                o.x = fmaxf(acc2[mt][nt][h * 2 + 0] + bv.x, 0.f);
                o.y = fmaxf(acc2[mt][nt][h * 2 + 1] + bv.y, 0.f);
                *(float2*)&out[((size_t)b * NN + row0 + r) * OUTD + col] = o;
            }
        }
    }
}

// ---------------------------------------------------------------------------
extern "C" void kernel_launch(void* const* d_in, const int* in_sizes, int n_in,
                              void* d_out, int out_size) {
    const float *x = nullptr, *A = nullptr, *Kmat = nullptr, *bias = nullptr;
    for (int i = 0; i < n_in; i++) {
        switch (in_sizes[i]) {
            case B_ * NN * FDIM:  x    = (const float*)d_in[i]; break;
            case B_ * NN * NN:    A    = (const float*)d_in[i]; break;
            case 3 * FDIM * OUTD: Kmat = (const float*)d_in[i]; break;
            case OUTD:            bias = (const float*)d_in[i]; break;
        }
    }
    float* out = (float*)d_out;

    static bool attr_set = false;
    if (!attr_set) {
        cudaFuncSetAttribute(fused_mma_kernel,
                             cudaFuncAttributeMaxDynamicSharedMemorySize, SMEM_BYTES);
        attr_set = true;
    }

    deg_prep_kernel<<<(B_ * NN * 32 + 255) / 256, 256>>>(A);
    prep_kernel<<<dim3(NN / 128, B_), 256>>>(x);
    fused_mma_kernel<<<dim3(NN / MROWS, B_), 256, SMEM_BYTES>>>(A, x, Kmat, bias, out);
}

// round 15
// speedup vs baseline: 1.3084x; 1.3084x over previous
#include <cuda_runtime.h>
#include <cuda_fp16.h>
#include <cstdint>
#include <cstddef>

#define EPS   1e-6f
#define B_    16
#define NN    1024
#define FDIM  64
#define OUTD  128
#define KC    32
#define NCTAS 128

// strides in b32 units (bank-conflict-free: (20*lr+lc) mod 32 all-distinct)
#define SA_STRH 20
#define OC_STRH 100
#define KM_STRH 100

// smem layout (bytes)
#define OFF_ADIAG 0
#define OFF_INV   512
#define OFF_SROW  1024
#define OFF_RS    1536
#define OFF_DYN   2048
#define ASTG_B    (128 * 80)                 // 10240
#define BSTG_B    (64 * 80)                  // 5120
#define STG_B     (ASTG_B + BSTG_B)          // 15360
#define OFF_STAGE(s) (OFF_DYN + (s) * STG_B) // 3 stages end at 48128
#define OFF_OC    OFF_DYN                    // 128*400 = 51200
#define OFF_KM    (OFF_DYN + 51200)          // 53248
#define SMEM_BYTES (OFF_KM + 128 * KM_STRH * 4)   // 104448

__device__ __half g_Bx[(size_t)B_ * 64 * NN];   // [b][f:64][k] fp16(x^T)
__device__ __half g_B2[(size_t)B_ * 64 * NN];   // [b][f:64][k] fp16(s_k * x)
__device__ volatile unsigned g_bar[2];

__device__ __forceinline__ uint32_t smem_u32(const void* p) {
    uint32_t a;
    asm("{ .reg .u64 t; cvta.to.shared.u64 t, %1; cvt.u32.u64 %0, t; }"
        : "=r"(a) : "l"(p));
    return a;
}
__device__ __forceinline__ void cp_async16(uint32_t saddr, const void* g) {
    asm volatile("cp.async.cg.shared.global [%0], [%1], 16;"
                 :: "r"(saddr), "l"(g) : "memory");
}
#define CP_COMMIT() asm volatile("cp.async.commit_group;" ::: "memory")
#define CP_WAIT0()  asm volatile("cp.async.wait_group 0;" ::: "memory")
#define MEMBAR_CTA() asm volatile("membar.cta;" ::: "memory")
__device__ __forceinline__ void bar_sync512(int id) {
    asm volatile("bar.sync %0, 512;" :: "r"(id) : "memory");
}
__device__ __forceinline__ void bar_arrive512(int id) {
    asm volatile("bar.arrive %0, 512;" :: "r"(id) : "memory");
}
__device__ __forceinline__ void bar_sync_n(int id, int n) {
    asm volatile("bar.sync %0, %1;" :: "r"(id), "r"(n) : "memory");
}
__device__ __forceinline__ uint32_t h2pack(float lo, float hi) {
    __half2 h = __floats2half2_rn(lo, hi);
    return *(uint32_t*)&h;
}
__device__ __forceinline__ float h2f_rn(float v) {
    return __half2float(__float2half_rn(v));
}
__device__ __forceinline__ float h2sum(uint32_t u) {
    __half2 h = *(__half2*)&u;
    float2 f = __half22float2(h);
    return f.x + f.y;
}
__device__ __forceinline__ void mma_f16(float* c, const uint32_t* a, const uint32_t* b) {
    asm volatile(
        "mma.sync.aligned.m16n8k16.row.col.f32.f16.f16.f32 "
        "{%0,%1,%2,%3}, {%4,%5,%6,%7}, {%8,%9}, {%0,%1,%2,%3};"
        : "+f"(c[0]), "+f"(c[1]), "+f"(c[2]), "+f"(c[3])
        : "r"(a[0]), "r"(a[1]), "r"(a[2]), "r"(a[3]), "r"(b[0]), "r"(b[1]));
}
__device__ __forceinline__ void grid_sync(int i) {
    __syncthreads();
    if (threadIdx.x == 0) {
        __threadfence();
        atomicAdd((unsigned*)&g_bar[i], 1u);
        while (g_bar[i] < (unsigned)NCTAS)
            asm volatile("nanosleep.u32 128;");
        __threadfence();
    }
    __syncthreads();
}

__global__ void reset_kernel() { g_bar[0] = 0; g_bar[1] = 0; }

// Build g_B2 slice (own k-rows): g_B2[f][k] = rn16(s_k * rn16(x_kf))
__device__ __forceinline__ void b2_build(const float* smf, int b, int row0, int tid) {
    const uint32_t* src = (const uint32_t*)(g_Bx + (size_t)b * 64 * NN) + (row0 >> 1);
    uint32_t* dst = (uint32_t*)(g_B2 + (size_t)b * 64 * NN) + (row0 >> 1);
#pragma unroll
    for (int q = 0; q < 8; q++) {
        int e = tid + q * 512;           // 0..4095
        int f = e >> 6, kp = e & 63;
        uint32_t v = src[f * 512 + kp];
        __half2 h = *(__half2*)&v;
        float2 xf = __half22float2(h);
        float s0 = smf[(OFF_SROW >> 2) + 2 * kp];
        float s1 = smf[(OFF_SROW >> 2) + 2 * kp + 1];
        dst[f * 512 + kp] = h2pack(s0 * xf.x, s1 * xf.y);
    }
}

// ---------------------------------------------------------------------------
// Mega kernel. 128 CTAs (1/SM, all resident). Warps 0-7 consumers, 8-15
// producers. Pass A: D1 = A@x (rowsums harvested from A fragments);
// mid-phase: deg -> s/inv, build s*x operand; pass B: D3 = A@(s*x).
// Then epilogue -> ocat fp16 -> GEMM2 -> bias+relu.
// ---------------------------------------------------------------------------
__global__ __launch_bounds__(512, 1)
void mega_kernel(const float* __restrict__ A, const float* __restrict__ x,
                 const float* __restrict__ Kmat, const float* __restrict__ bias,
                 float* __restrict__ out) {
    extern __shared__ char smc[];
    float* smf = (float*)smc;
    const uint32_t sb = smem_u32(smc);
    const int tid  = threadIdx.x;
    const int wid  = tid >> 5;
    const int lane = tid & 31;
    const int b    = blockIdx.y;
    const int row0 = blockIdx.x * 128;
    const int lr = lane >> 2;
    const int lc = lane & 3;

    const float* Ab = A + (size_t)b * NN * NN;
    const float* xb = x + (size_t)b * NN * FDIM;

    // ================= PRE-PHASE: build g_Bx slice + adiag ==================
    {
        float* xt = smf + (OFF_DYN >> 2);           // [128][65] floats
        const float* xs = xb + (size_t)row0 * FDIM;
#pragma unroll
        for (int q = 0; q < 4; q++) {
            int e = tid + q * 512;                  // 2048 float4
            int row = e >> 4, c4 = (e & 15) * 4;
            float4 v = *(const float4*)&xs[(size_t)row * FDIM + c4];
            xt[row * 65 + c4] = v.x;  xt[row * 65 + c4 + 1] = v.y;
            xt[row * 65 + c4 + 2] = v.z; xt[row * 65 + c4 + 3] = v.w;
        }
        if (tid < 128) {
            int grow = row0 + tid;
            smf[(OFF_ADIAG >> 2) + tid] = h2f_rn(__ldg(&Ab[(size_t)grow * NN + grow]));
        }
        __syncthreads();
        uint32_t* dBx = (uint32_t*)(g_Bx + (size_t)b * 64 * NN) + (row0 >> 1);
#pragma unroll
        for (int q = 0; q < 8; q++) {
            int e = tid + q * 512;                  // 4096 half2
            int f = e >> 6, kp = e & 63;
            dBx[f * 512 + kp] = h2pack(xt[(2 * kp) * 65 + f], xt[(2 * kp + 1) * 65 + f]);
        }
    }
    grid_sync(0);

    if (wid >= 8) {
        // ============================ PRODUCER ==============================
        const int ptid = tid - 256;
        const int arow = ptid >> 3;                 // 0..31 (+32q)
        const int acol = (ptid & 7) * 4;
        const int brow = ptid >> 2;                 // 0..63 (f row)
        const int bch  = ptid & 3;
        const float* gA = Ab + (size_t)(row0 + arow) * NN + acol;
        const __half* gBxs = g_Bx + (size_t)b * 64 * NN + (size_t)brow * NN + bch * 8;
        const __half* gB2s = g_B2 + (size_t)b * 64 * NN + (size_t)brow * NN + bch * 8;

        for (int it = 0; it < 64; ++it) {
            if (it == 32) {                          // mid-phase join
                __syncthreads();
                b2_build(smf, b, row0, tid);
                grid_sync(1);
            }
            const int s = it % 3;
            const int k0 = (it & 31) * KC;
            if (it >= 3) bar_sync512(4 + s);
            float4 va[4];
#pragma unroll
            for (int q = 0; q < 4; q++)
                va[q] = *(const float4*)(gA + k0 + (size_t)q * 32 * NN);
            const __half* gBsrc = (it < 32 ? gBxs : gB2s) + k0;
            cp_async16(sb + OFF_STAGE(s) + ASTG_B + brow * 80 + bch * 16, gBsrc);
            CP_COMMIT();
            char* dA = smc + OFF_STAGE(s);
#pragma unroll
            for (int q = 0; q < 4; q++) {
                uint2 w;
                w.x = h2pack(va[q].x, va[q].y);
                w.y = h2pack(va[q].z, va[q].w);
                *(uint2*)(dA + (arow + 32 * q) * 80 + acol * 2) = w;
            }
            CP_WAIT0();
            MEMBAR_CTA();
            bar_arrive512(1 + s);
        }
        // stage KmatT fp16 [n:128][k:192] while consumers drain tail
        {
            uint32_t* km = (uint32_t*)(smc + OFF_KM);
#pragma unroll 1
            for (int e = ptid; e < 128 * 96; e += 256) {
                int n = e / 96;
                int kp = e - n * 96;
                float v0 = __ldg(&Kmat[(size_t)(2 * kp) * 128 + n]);
                float v1 = __ldg(&Kmat[(size_t)(2 * kp + 1) * 128 + n]);
                km[n * KM_STRH + kp] = h2pack(v0, v1);
            }
        }
    } else {
        // ============================ CONSUMER ==============================
        const int wm = wid >> 1;                     // 0..3
        const int wn = wid & 1;                      // 0..1
        const int mm = wm * 32;
        const int n4 = wn * 32;                      // f columns n4..n4+31

        float accA[2][4][4], accB[2][4][4];
#pragma unroll
        for (int mt = 0; mt < 2; mt++)
#pragma unroll
            for (int nt = 0; nt < 4; nt++)
#pragma unroll
                for (int q = 0; q < 4; q++) { accA[mt][nt][q] = 0.f; accB[mt][nt][q] = 0.f; }
        float rs[4] = {0.f, 0.f, 0.f, 0.f};          // [mt][row-half] fp32 rowsums

        // ---- pass A: D1 = A @ x, harvest rowsums from A fragments
        for (int it = 0; it < 32; ++it) {
            const int s = it % 3;
            bar_sync512(1 + s);
            const uint32_t* sA = (const uint32_t*)(smc + OFF_STAGE(s));
            const uint32_t* sB = sA + (ASTG_B >> 2);
#pragma unroll
            for (int ks = 0; ks < 2; ks++) {
                const int kb = ks * 8;
                uint32_t af[2][4], bf2[4][2];
#pragma unroll
                for (int mt = 0; mt < 2; mt++) {
                    const uint32_t* p = sA + (mm + mt * 16 + lr) * SA_STRH + kb + lc;
                    af[mt][0] = p[0];
                    af[mt][1] = p[8 * SA_STRH];
                    af[mt][2] = p[4];
                    af[mt][3] = p[8 * SA_STRH + 4];
                }
                if (wn == 0) {                       // free rowsum (fma pipe)
#pragma unroll
                    for (int mt = 0; mt < 2; mt++) {
                        rs[mt * 2 + 0] += h2sum(af[mt][0]) + h2sum(af[mt][2]);
                        rs[mt * 2 + 1] += h2sum(af[mt][1]) + h2sum(af[mt][3]);
                    }
                }
#pragma unroll
                for (int nt = 0; nt < 4; nt++) {
                    const uint32_t* p = sB + (n4 + nt * 8 + lr) * SA_STRH + kb + lc;
                    bf2[nt][0] = p[0];
                    bf2[nt][1] = p[4];
                }
#pragma unroll
                for (int mt = 0; mt < 2; mt++)
#pragma unroll
                    for (int nt = 0; nt < 4; nt++)
                        mma_f16(accA[mt][nt], af[mt], bf2[nt]);
            }
            bar_arrive512(4 + s);
        }

        // ---- mid-phase: rowsums -> deg -> inv/s ; build B2 ; grid sync
        if (wn == 0) {
#pragma unroll
            for (int mt = 0; mt < 2; mt++) {
                float v0 = rs[mt * 2 + 0];
                float v1 = rs[mt * 2 + 1];
                v0 += __shfl_xor_sync(0xFFFFFFFFu, v0, 1);
                v0 += __shfl_xor_sync(0xFFFFFFFFu, v0, 2);
                v1 += __shfl_xor_sync(0xFFFFFFFFu, v1, 1);
                v1 += __shfl_xor_sync(0xFFFFFFFFu, v1, 2);
                if (lc == 0) {
                    smf[(OFF_RS >> 2) + mm + mt * 16 + lr]     = v0;
                    smf[(OFF_RS >> 2) + mm + mt * 16 + lr + 8] = v1;
                }
            }
        }
        bar_sync_n(7, 256);
        if (tid < 128) {
            float rsv = smf[(OFF_RS >> 2) + tid];
            float ad  = smf[(OFF_ADIAG >> 2) + tid];
            float deg = rsv - ad + 1.0f;
            smf[(OFF_INV >> 2) + tid]  = 1.0f / (EPS + deg);
            smf[(OFF_SROW >> 2) + tid] = 1.0f / (EPS + sqrtf(deg));
        }
        __syncthreads();
        b2_build(smf, b, row0, tid);
        grid_sync(1);

        // ---- pass B: D3 = A @ (s*x)
        for (int it = 32; it < 64; ++it) {
            const int s = it % 3;
            bar_sync512(1 + s);
            const uint32_t* sA = (const uint32_t*)(smc + OFF_STAGE(s));
            const uint32_t* sB = sA + (ASTG_B >> 2);
#pragma unroll
            for (int ks = 0; ks < 2; ks++) {
                const int kb = ks * 8;
                uint32_t af[2][4], bf2[4][2];
#pragma unroll
                for (int mt = 0; mt < 2; mt++) {
                    const uint32_t* p = sA + (mm + mt * 16 + lr) * SA_STRH + kb + lc;
                    af[mt][0] = p[0];
                    af[mt][1] = p[8 * SA_STRH];
                    af[mt][2] = p[4];
                    af[mt][3] = p[8 * SA_STRH + 4];
                }
#pragma unroll
                for (int nt = 0; nt < 4; nt++) {
                    const uint32_t* p = sB + (n4 + nt * 8 + lr) * SA_STRH + kb + lc;
                    bf2[nt][0] = p[0];
                    bf2[nt][1] = p[4];
                }
#pragma unroll
                for (int mt = 0; mt < 2; mt++)
#pragma unroll
                    for (int nt = 0; nt < 4; nt++)
                        mma_f16(accB[mt][nt], af[mt], bf2[nt]);
            }
            bar_arrive512(4 + s);
        }
        bar_sync_n(7, 256);                          // stages dead for all consumers

        // ---- epilogue: o1/o2/o3 -> ocat fp16 [128][192]
        uint32_t* oc = (uint32_t*)(smc + OFF_OC);
#pragma unroll
        for (int mt = 0; mt < 2; mt++) {
#pragma unroll
            for (int nt = 0; nt < 4; nt++) {
                const int f = n4 + nt * 8 + lc * 2;
#pragma unroll
                for (int h = 0; h < 2; h++) {
                    const int r = mm + mt * 16 + lr + h * 8;
                    const float ad  = smf[(OFF_ADIAG >> 2) + r];
                    const float inv = smf[(OFF_INV >> 2) + r];
                    const float sv  = smf[(OFF_SROW >> 2) + r];
                    const float c1a = accA[mt][nt][h * 2 + 0];
                    const float c1b = accA[mt][nt][h * 2 + 1];
                    const float c3a = accB[mt][nt][h * 2 + 0];
                    const float c3b = accB[mt][nt][h * 2 + 1];
                    float2 xv = *(const float2*)&xb[(size_t)(row0 + r) * FDIM + f];
                    float xhx = h2f_rn(xv.x), xhy = h2f_rn(xv.y);
                    float o1a = c1a - ad * xhx;
                    float o1b = c1b - ad * xhy;
                    float o2a = inv * (o1a + xv.x);
                    float o2b = inv * (o1b + xv.y);
                    float sxx = h2f_rn(sv * xhx), sxy = h2f_rn(sv * xhy);
                    float o3a = sv * c3a - sv * ad * sxx + sv * sv * xv.x;
                    float o3b = sv * c3b - sv * ad * sxy + sv * sv * xv.y;
                    oc[r * OC_STRH + (f >> 1)]         = h2pack(o1a, o1b);
                    oc[r * OC_STRH + ((64 + f) >> 1)]  = h2pack(o2a, o2b);
                    oc[r * OC_STRH + ((128 + f) >> 1)] = h2pack(o3a, o3b);
                }
            }
        }
    }
    __syncthreads();   // OC (consumers) + KM (producers) ready

    // ---- GEMM2: out[128,128] = ocat[128,192] @ KmatT^T (fp16, 12 k-steps)
    const int mmg = (wid >> 2) * 32;
    const int n4g = (wid & 3) * 32;
    const uint32_t* ocp = (const uint32_t*)(smc + OFF_OC);
    const uint32_t* kmp = (const uint32_t*)(smc + OFF_KM);
    float acc2[2][4][4];
#pragma unroll
    for (int mt = 0; mt < 2; mt++)
#pragma unroll
        for (int nt = 0; nt < 4; nt++)
#pragma unroll
            for (int q = 0; q < 4; q++) acc2[mt][nt][q] = 0.f;

#pragma unroll
    for (int ks = 0; ks < 12; ks++) {
        const int kb = ks * 8;
        uint32_t af[2][4], bf2[4][2];
#pragma unroll
        for (int mt = 0; mt < 2; mt++) {
            const uint32_t* p = ocp + (mmg + mt * 16 + lr) * OC_STRH + kb + lc;
            af[mt][0] = p[0];
            af[mt][1] = p[8 * OC_STRH];
            af[mt][2] = p[4];
            af[mt][3] = p[8 * OC_STRH + 4];
        }
#pragma unroll
        for (int nt = 0; nt < 4; nt++) {
            const uint32_t* p = kmp + (n4g + nt * 8 + lr) * KM_STRH + kb + lc;
            bf2[nt][0] = p[0];
            bf2[nt][1] = p[4];
        }
#pragma unroll
        for (int mt = 0; mt < 2; mt++)
#pragma unroll
            for (int nt = 0; nt < 4; nt++)
                mma_f16(acc2[mt][nt], af[mt], bf2[nt]);
    }

    // ---- bias + relu + store
#pragma unroll
    for (int mt = 0; mt < 2; mt++) {
#pragma unroll
        for (int nt = 0; nt < 4; nt++) {
            const int col = n4g + nt * 8 + lc * 2;
            float2 bv = *(const float2*)&bias[col];
#pragma unroll
            for (int h = 0; h < 2; h++) {
                const int r = mmg + mt * 16 + lr + h * 8;
                float2 o;
                o.x = fmaxf(acc2[mt][nt][h * 2 + 0] + bv.x, 0.f);
                o.y = fmaxf(acc2[mt][nt][h * 2 + 1] + bv.y, 0.f);
                *(float2*)&out[((size_t)b * NN + row0 + r) * OUTD + col] = o;
            }
        }
    }
}

// ---------------------------------------------------------------------------
extern "C" void kernel_launch(void* const* d_in, const int* in_sizes, int n_in,
                              void* d_out, int out_size) {
    const float *x = nullptr, *A = nullptr, *Kmat = nullptr, *bias = nullptr;
    for (int i = 0; i < n_in; i++) {
        switch (in_sizes[i]) {
            case B_ * NN * FDIM:  x    = (const float*)d_in[i]; break;
            case B_ * NN * NN:    A    = (const float*)d_in[i]; break;
            case 3 * FDIM * OUTD: Kmat = (const float*)d_in[i]; break;
            case OUTD:            bias = (const float*)d_in[i]; break;
        }
    }
    float* out = (float*)d_out;

    static bool attr_set = false;
    if (!attr_set) {
        cudaFuncSetAttribute(mega_kernel,
                             cudaFuncAttributeMaxDynamicSharedMemorySize, SMEM_BYTES);
        attr_set = true;
    }

    reset_kernel<<<1, 1>>>();
    mega_kernel<<<dim3(NN / 128, B_), 512, SMEM_BYTES>>>(A, x, Kmat, bias, out);
}

// round 16
// speedup vs baseline: 1.3488x; 1.0309x over previous
#include <cuda_runtime.h>
#include <cstdint>
#include <cstddef>

#define EPS   1e-6f
#define B_    16
#define NN    1024
#define FDIM  64
#define OUTD  128
#define KC    32
#define NITER (NN / KC)

// smem strides (floats): A-operand stride ≡ 4 (mod 32), B-operand ≡ 8 (mod 32)
#define SA_STR 36
#define SB_STR 136
#define OC_STR 196
#define SK_STR 136

// smem layout (float offsets)
#define OFF_ADIAG 0
#define OFF_INV   128
#define OFF_SROW  256
#define OFF_DYN   384
#define ASTG      (128 * SA_STR)            // 4608
#define BSTG      (KC * SB_STR)             // 4352
#define STG       (ASTG + BSTG)             // 8960 per stage
#define OFF_STAGE(s) (OFF_DYN + (s) * STG)
#define OFF_OC    OFF_DYN                   // 25088 floats (inside 3 stages)
#define OFF_KM    (OFF_DYN + 3 * STG)       // 27264
#define SMEM_FLOATS (OFF_KM + 192 * SK_STR) // 53376
#define SMEM_BYTES  (SMEM_FLOATS * 4)       // 213504

__device__ float g_inv[B_ * NN];
__device__ float g_s[B_ * NN];
__device__ float g_B[(size_t)B_ * NN * 128];   // [b][k][x(tf32)|s*x(tf32)]

__device__ __forceinline__ uint32_t smem_u32(const void* p) {
    uint32_t a;
    asm("{ .reg .u64 t; cvta.to.shared.u64 t, %1; cvt.u32.u64 %0, t; }"
        : "=r"(a) : "l"(p));
    return a;
}
__device__ __forceinline__ void cp_async16(uint32_t saddr, const void* g) {
    asm volatile("cp.async.cg.shared.global [%0], [%1], 16;"
                 :: "r"(saddr), "l"(g) : "memory");
}
#define CP_COMMIT() asm volatile("cp.async.commit_group;" ::: "memory")
#define CP_WAIT1()  asm volatile("cp.async.wait_group 1;" ::: "memory")
#define CP_WAIT0()  asm volatile("cp.async.wait_group 0;" ::: "memory")
#define MEMBAR_CTA() asm volatile("membar.cta;" ::: "memory")

__device__ __forceinline__ void bar_sync512(int id) {
    asm volatile("bar.sync %0, 512;" :: "r"(id) : "memory");
}
__device__ __forceinline__ void bar_arrive512(int id) {
    asm volatile("bar.arrive %0, 512;" :: "r"(id) : "memory");
}
__device__ __forceinline__ void bar_sync_n(int id, int n) {
    asm volatile("bar.sync %0, %1;" :: "r"(id), "r"(n) : "memory");
}
__device__ __forceinline__ float to_tf32(float v) {
    float r;
    asm("cvt.rna.tf32.f32 %0, %1;" : "=f"(r) : "f"(v));
    return r;
}
__device__ __forceinline__ float4 tf32x4(float4 v) {
    v.x = to_tf32(v.x); v.y = to_tf32(v.y);
    v.z = to_tf32(v.z); v.w = to_tf32(v.w);
    return v;
}
__device__ __forceinline__ void mma_tf32(float* c, const uint32_t* a, const uint32_t* b) {
    asm volatile(
        "mma.sync.aligned.m16n8k8.row.col.f32.tf32.tf32.f32 "
        "{%0,%1,%2,%3}, {%4,%5,%6,%7}, {%8,%9}, {%0,%1,%2,%3};"
        : "+f"(c[0]), "+f"(c[1]), "+f"(c[2]), "+f"(c[3])
        : "r"(a[0]), "r"(a[1]), "r"(a[2]), "r"(a[3]), "r"(b[0]), "r"(b[1]));
}

// ---------------------------------------------------------------------------
// Kernel 1: deg + B-prep merged (R10-proven). One warp per (b,k) row:
// rowsum(A) -> g_inv/g_s ; write g_B row = [tf32(x) | tf32(s*x)].
// ---------------------------------------------------------------------------
__global__ void deg_prep_kernel(const float* __restrict__ A,
                                const float* __restrict__ x) {
    int warp = (blockIdx.x * blockDim.x + threadIdx.x) >> 5;
    int lane = threadIdx.x & 31;
    if (warp >= B_ * NN) return;
    const float* row = A + (size_t)warp * NN;
    float sum = 0.f;
    const float4* r4 = (const float4*)row;
#pragma unroll
    for (int w = 0; w < 8; w++) {
        float4 v = r4[w * 32 + lane];
        sum += v.x + v.y + v.z + v.w;
    }
#pragma unroll
    for (int off = 16; off > 0; off >>= 1)
        sum += __shfl_down_sync(0xFFFFFFFFu, sum, off);
    float sv;
    if (lane == 0) {
        float deg = sum - row[warp % NN] + 1.0f;
        g_inv[warp] = 1.0f / (EPS + deg);
        sv = 1.0f / (EPS + sqrtf(deg));
        g_s[warp] = sv;
    }
    sv = __shfl_sync(0xFFFFFFFFu, sv, 0);
    float2 v = *(const float2*)&x[(size_t)warp * FDIM + lane * 2];
    float* dst = &g_B[(size_t)warp * 128];
    *(float2*)&dst[lane * 2]      = make_float2(to_tf32(v.x), to_tf32(v.y));
    *(float2*)&dst[64 + lane * 2] = make_float2(to_tf32(sv * v.x), to_tf32(sv * v.y));
}

// ---------------------------------------------------------------------------
// Kernel 2: fused, warp-specialized, producer leads consumers by one stage.
// Warps 0-7 consumers (64x32 tiles), warps 8-15 producers.
// full[s] = bar 1+s ; empty[s] = bar 4+s.
// ---------------------------------------------------------------------------
__global__ __launch_bounds__(512, 1)
void fused_mma_kernel(const float* __restrict__ A, const float* __restrict__ x,
                      const float* __restrict__ Kmat, const float* __restrict__ bias,
                      float* __restrict__ out) {
    extern __shared__ float sm[];
    const uint32_t sb = smem_u32(sm);
    const int tid  = threadIdx.x;
    const int wid  = tid >> 5;
    const int lane = tid & 31;
    const int b    = blockIdx.y;
    const int row0 = blockIdx.x * 128;
    const int lr = lane >> 2;
    const int lc = lane & 3;

    const float* Ab = A + (size_t)b * NN * NN;
    const float* xb = x + (size_t)b * NN * FDIM;
    const float* Bb = g_B + (size_t)b * NN * 128;

    if (wid >= 8) {
        // ---------------- PRODUCER ----------------
        const int ptid = tid - 256;
        const int arow = ptid >> 3;              // 0..31 (+32q)
        const int acol = (ptid & 7) * 4;
        const int bkr  = ptid >> 5;              // 0..7  (+8q)
        const int bcol = (ptid & 31) * 4;
        const float* gA = Ab + (size_t)(row0 + arow) * NN + acol;

        if (ptid < 128) {
            int grow = row0 + ptid;
            sm[OFF_ADIAG + ptid] = __ldg(&Ab[(size_t)grow * NN + grow]);
            sm[OFF_INV + ptid]   = g_inv[b * NN + grow];
            sm[OFF_SROW + ptid]  = g_s[b * NN + grow];
        }

        float4 va[4];
        // --- prologue: stage 0, stage 1; prefetch A(2)
#pragma unroll
        for (int st = 0; st < 2; st++) {
            const int k0 = st * KC;
#pragma unroll
            for (int q = 0; q < 4; q++)
                va[q] = *(const float4*)(gA + k0 + (size_t)q * 32 * NN);
            float* dA = &sm[OFF_STAGE(st)];
#pragma unroll
            for (int q = 0; q < 4; q++)
                *(float4*)&dA[(arow + 32 * q) * SA_STR + acol] = tf32x4(va[q]);
            uint32_t sBb = sb + (OFF_STAGE(st) + ASTG) * 4;
#pragma unroll
            for (int q = 0; q < 4; q++)
                cp_async16(sBb + ((bkr + 8 * q) * SB_STR + bcol) * 4,
                           Bb + (size_t)(k0 + bkr + 8 * q) * 128 + bcol);
            CP_COMMIT();
        }
#pragma unroll
        for (int q = 0; q < 4; q++)
            va[q] = *(const float4*)(gA + 2 * KC + (size_t)q * 32 * NN);
        CP_WAIT1();            // B(0) landed
        MEMBAR_CTA();
        bar_arrive512(1 + 0);  // full[0]

        // --- mainloop: at iter it, fill stage it+2, publish full[it+1]
        for (int it = 0; it < NITER; ++it) {
            if (it + 2 < NITER) {
                const int s2 = (it + 2) % 3;
                if (it >= 1) bar_sync512(4 + s2);           // stage reuse gate
                float* dA = &sm[OFF_STAGE(s2)];
#pragma unroll
                for (int q = 0; q < 4; q++)                  // va = A(it+2), arrived
                    *(float4*)&dA[(arow + 32 * q) * SA_STR + acol] = tf32x4(va[q]);
                const int k0 = (it + 2) * KC;
                uint32_t sBb = sb + (OFF_STAGE(s2) + ASTG) * 4;
#pragma unroll
                for (int q = 0; q < 4; q++)
                    cp_async16(sBb + ((bkr + 8 * q) * SB_STR + bcol) * 4,
                               Bb + (size_t)(k0 + bkr + 8 * q) * 128 + bcol);
                CP_COMMIT();
                if (it + 3 < NITER) {
                    const int kn = (it + 3) * KC;
#pragma unroll
                    for (int q = 0; q < 4; q++)
                        va[q] = *(const float4*)(gA + kn + (size_t)q * 32 * NN);
                }
            }
            if (it + 1 < NITER) {
                if (it + 2 < NITER) { CP_WAIT1(); } else { CP_WAIT0(); }
                MEMBAR_CTA();
                bar_arrive512(1 + (it + 1) % 3);             // full[it+1]
            }
        }
        // stage Kmat (tf32) while consumers drain the tail
        {
            const float4* src = (const float4*)Kmat;
#pragma unroll 1
            for (int i4 = ptid; i4 < 192 * 128 / 4; i4 += 256) {
                int row = i4 >> 5, c4 = (i4 & 31) * 4;
                *(float4*)&sm[OFF_KM + row * SK_STR + c4] = tf32x4(src[i4]);
            }
        }
    } else {
        // ---------------- CONSUMER ----------------
        const int m_base = (wid >> 2) * 64;
        const int n_base = (wid & 3) * 32;
        const bool scaled = (n_base >= 64);
        const int f_base = scaled ? n_base - 64 : n_base;

        float acc[4][4][4];
#pragma unroll
        for (int mt = 0; mt < 4; mt++)
#pragma unroll
            for (int nt = 0; nt < 4; nt++)
#pragma unroll
                for (int q = 0; q < 4; q++) acc[mt][nt][q] = 0.f;

        for (int it = 0; it < NITER; ++it) {
            const int s = it % 3;
            bar_sync512(1 + s);                              // full[it]
            const float* sA = &sm[OFF_STAGE(s)];
            const float* sB = sA + ASTG;
#pragma unroll
            for (int ks = 0; ks < 4; ks++) {
                const int k = ks * 8;
                uint32_t af[4][4], bf[4][2];
#pragma unroll
                for (int mt = 0; mt < 4; mt++) {
                    const float* p = sA + (m_base + mt * 16 + lr) * SA_STR + k + lc;
                    af[mt][0] = __float_as_uint(p[0]);
                    af[mt][1] = __float_as_uint(p[8 * SA_STR]);
                    af[mt][2] = __float_as_uint(p[4]);
                    af[mt][3] = __float_as_uint(p[8 * SA_STR + 4]);
                }
#pragma unroll
                for (int nt = 0; nt < 4; nt++) {
                    const float* p = sB + (k + lc) * SB_STR + n_base + nt * 8 + lr;
                    bf[nt][0] = __float_as_uint(p[0]);
                    bf[nt][1] = __float_as_uint(p[4 * SB_STR]);
                }
#pragma unroll
                for (int mt = 0; mt < 4; mt++)
#pragma unroll
                    for (int nt = 0; nt < 4; nt++)
                        mma_tf32(acc[mt][nt], af[mt], bf[nt]);
            }
            bar_arrive512(4 + s);                            // empty[s]
        }
        bar_sync_n(7, 256);                                  // consumers done reading

        // epilogue 1: analytic diagonal fix + scalings -> ocat [128][192]
#pragma unroll
        for (int mt = 0; mt < 4; mt++) {
#pragma unroll
            for (int nt = 0; nt < 4; nt++) {
                const int f = f_base + nt * 8 + lc * 2;
#pragma unroll
                for (int h = 0; h < 2; h++) {
                    const int r = m_base + mt * 16 + lr + h * 8;
                    const float ad = sm[OFF_ADIAG + r];
                    const float c0 = acc[mt][nt][h * 2 + 0];
                    const float c1 = acc[mt][nt][h * 2 + 1];
                    float2 xv = *(const float2*)&xb[(size_t)(row0 + r) * FDIM + f];
                    if (!scaled) {
                        const float inv = sm[OFF_INV + r];
                        float o1a = c0 - ad * xv.x;
                        float o1b = c1 - ad * xv.y;
                        float2 w1 = make_float2(to_tf32(o1a), to_tf32(o1b));
                        float2 w2 = make_float2(to_tf32(inv * (o1a + xv.x)),
                                                to_tf32(inv * (o1b + xv.y)));
                        *(float2*)&sm[OFF_OC + r * OC_STR + f]      = w1;
                        *(float2*)&sm[OFF_OC + r * OC_STR + 64 + f] = w2;
                    } else {
                        const float sv = sm[OFF_SROW + r];
                        const float t = sv * sv * (1.0f - ad);
                        float2 w3 = make_float2(to_tf32(sv * c0 + t * xv.x),
                                                to_tf32(sv * c1 + t * xv.y));
                        *(float2*)&sm[OFF_OC + r * OC_STR + 128 + f] = w3;
                    }
                }
            }
        }
    }
    __syncthreads();   // OC + KM ready; all 16 warps join

    // ---- GEMM2: out[128,128] = ocat[128,192] @ Kmat[192,128]
    const int mm = (wid >> 2) * 32;
    const int n4 = (wid & 3) * 32;
    float acc2[2][4][4];
#pragma unroll
    for (int mt = 0; mt < 2; mt++)
#pragma unroll
        for (int nt = 0; nt < 4; nt++)
#pragma unroll
            for (int q = 0; q < 4; q++) acc2[mt][nt][q] = 0.f;

#pragma unroll
    for (int ks = 0; ks < 24; ks++) {
        const int k = ks * 8;
        uint32_t af[2][4], bf[4][2];
#pragma unroll
        for (int mt = 0; mt < 2; mt++) {
            const float* p = &sm[OFF_OC + (mm + mt * 16 + lr) * OC_STR + k + lc];
            af[mt][0] = __float_as_uint(p[0]);
            af[mt][1] = __float_as_uint(p[8 * OC_STR]);
            af[mt][2] = __float_as_uint(p[4]);
            af[mt][3] = __float_as_uint(p[8 * OC_STR + 4]);
        }
#pragma unroll
        for (int nt = 0; nt < 4; nt++) {
            const float* p = &sm[OFF_KM + (k + lc) * SK_STR + n4 + nt * 8 + lr];
            bf[nt][0] = __float_as_uint(p[0]);
            bf[nt][1] = __float_as_uint(p[4 * SK_STR]);
        }
#pragma unroll
        for (int mt = 0; mt < 2; mt++)
#pragma unroll
            for (int nt = 0; nt < 4; nt++)
                mma_tf32(acc2[mt][nt], af[mt], bf[nt]);
    }

    // ---- bias + relu + store
#pragma unroll
    for (int mt = 0; mt < 2; mt++) {
#pragma unroll
        for (int nt = 0; nt < 4; nt++) {
            const int col = n4 + nt * 8 + lc * 2;
            float2 bv = *(const float2*)&bias[col];
#pragma unroll
            for (int h = 0; h < 2; h++) {
                const int r = mm + mt * 16 + lr + h * 8;
                float2 o;
                o.x = fmaxf(acc2[mt][nt][h * 2 + 0] + bv.x, 0.f);
                o.y = fmaxf(acc2[mt][nt][h * 2 + 1] + bv.y, 0.f);
                *(float2*)&out[((size_t)b * NN + row0 + r) * OUTD + col] = o;
            }
        }
    }
}

// ---------------------------------------------------------------------------
extern "C" void kernel_launch(void* const* d_in, const int* in_sizes, int n_in,
                              void* d_out, int out_size) {
    const float *x = nullptr, *A = nullptr, *Kmat = nullptr, *bias = nullptr;
    for (int i = 0; i < n_in; i++) {
        switch (in_sizes[i]) {
            case B_ * NN * FDIM:  x    = (const float*)d_in[i]; break;
            case B_ * NN * NN:    A    = (const float*)d_in[i]; break;
            case 3 * FDIM * OUTD: Kmat = (const float*)d_in[i]; break;
            case OUTD:            bias = (const float*)d_in[i]; break;
        }
    }
    float* out = (float*)d_out;

    static bool attr_set = false;
    if (!attr_set) {
        cudaFuncSetAttribute(fused_mma_kernel,
                             cudaFuncAttributeMaxDynamicSharedMemorySize, SMEM_BYTES);
        attr_set = true;
    }

    deg_prep_kernel<<<(B_ * NN * 32 + 255) / 256, 256>>>(A, x);
    fused_mma_kernel<<<dim3(NN / 128, B_), 512, SMEM_BYTES>>>(A, x, Kmat, bias, out);
}

// round 17
// speedup vs baseline: 1.3547x; 1.0044x over previous
#include <cuda_runtime.h>
#include <cuda_fp16.h>
#include <cstdint>
#include <cstddef>

#define EPS   1e-6f
#define B_    16
#define NN    1024
#define FDIM  64
#define OUTD  128
#define KC    32
#define NITER (NN / KC)
#define NCTAS 128

// strides in b32 units
#define SA_STRH 20
#define OC_STRH 100
#define KM_STRH 100

// smem layout (bytes)
#define OFF_ADIAG 0
#define OFF_INV   512
#define OFF_SROW  1024
#define OFF_DYN   1536
#define ASTG_B    (128 * SA_STRH * 4)
#define BSTG_B    (128 * SA_STRH * 4)
#define STG_B     (ASTG_B + BSTG_B)
#define OFF_STAGE(s) (OFF_DYN + (s) * STG_B)
#define OFF_OC    OFF_DYN
#define OFF_KM    (OFF_DYN + 3 * STG_B)
#define SMEM_BYTES (OFF_KM + 128 * KM_STRH * 4)   // 114176

__device__ float  g_inv[B_ * NN];
__device__ float  g_s[B_ * NN];
__device__ __half g_Bh[(size_t)B_ * 128 * NN];
__device__ volatile unsigned g_bar[2];

__device__ __forceinline__ uint32_t smem_u32(const void* p) {
    uint32_t a;
    asm("{ .reg .u64 t; cvta.to.shared.u64 t, %1; cvt.u32.u64 %0, t; }"
        : "=r"(a) : "l"(p));
    return a;
}
__device__ __forceinline__ void cp_async16(uint32_t saddr, const void* g) {
    asm volatile("cp.async.cg.shared.global [%0], [%1], 16;"
                 :: "r"(saddr), "l"(g) : "memory");
}
#define CP_COMMIT() asm volatile("cp.async.commit_group;" ::: "memory")
#define CP_WAIT1()  asm volatile("cp.async.wait_group 1;" ::: "memory")
#define CP_WAIT0()  asm volatile("cp.async.wait_group 0;" ::: "memory")
#define MEMBAR_CTA() asm volatile("membar.cta;" ::: "memory")
__device__ __forceinline__ void bar_sync512(int id) {
    asm volatile("bar.sync %0, 512;" :: "r"(id) : "memory");
}
__device__ __forceinline__ void bar_arrive512(int id) {
    asm volatile("bar.arrive %0, 512;" :: "r"(id) : "memory");
}
__device__ __forceinline__ void bar_sync_n(int id, int n) {
    asm volatile("bar.sync %0, %1;" :: "r"(id), "r"(n) : "memory");
}
__device__ __forceinline__ uint32_t h2pack(float lo, float hi) {
    __half2 h = __floats2half2_rn(lo, hi);
    return *(uint32_t*)&h;
}
__device__ __forceinline__ float h2f_rn(float v) {
    return __half2float(__float2half_rn(v));
}
__device__ __forceinline__ void mma_f16(float* c, const uint32_t* a, const uint32_t* b) {
    asm volatile(
        "mma.sync.aligned.m16n8k16.row.col.f32.f16.f16.f32 "
        "{%0,%1,%2,%3}, {%4,%5,%6,%7}, {%8,%9}, {%0,%1,%2,%3};"
        : "+f"(c[0]), "+f"(c[1]), "+f"(c[2]), "+f"(c[3])
        : "r"(a[0]), "r"(a[1]), "r"(a[2]), "r"(a[3]), "r"(b[0]), "r"(b[1]));
}
__device__ __forceinline__ void grid_sync(int i) {
    __syncthreads();
    if (threadIdx.x == 0) {
        __threadfence();
        atomicAdd((unsigned*)&g_bar[i], 1u);
        while (g_bar[i] < (unsigned)NCTAS)
            asm volatile("nanosleep.u32 128;");
        __threadfence();
    }
    __syncthreads();
}

__global__ void reset_kernel() { g_bar[0] = 0; g_bar[1] = 0; }

// ---------------------------------------------------------------------------
// Mega kernel: phase1 deg (own rows, warms L2) -> sync -> phase1.5 B-build
// -> sync -> phase2 warp-specialized fp16 dual-GEMM (producer leads by one)
// -> epilogue -> GEMM2.
// ---------------------------------------------------------------------------
__global__ __launch_bounds__(512, 1)
void mega_kernel(const float* __restrict__ A, const float* __restrict__ x,
                 const float* __restrict__ Kmat, const float* __restrict__ bias,
                 float* __restrict__ out) {
    extern __shared__ char smc[];
    float* smf = (float*)smc;
    const uint32_t sb = smem_u32(smc);
    const int tid  = threadIdx.x;
    const int wid  = tid >> 5;
    const int lane = tid & 31;
    const int b    = blockIdx.y;
    const int row0 = blockIdx.x * 128;
    const int lr = lane >> 2;
    const int lc = lane & 3;

    const float* Ab = A + (size_t)b * NN * NN;
    const float* xb = x + (size_t)b * NN * FDIM;
    const __half* Bb = g_Bh + (size_t)b * 128 * NN;

    // ================= PHASE 1: degree scalars for own 128 rows =============
#pragma unroll 1
    for (int rr = 0; rr < 8; rr++) {
        const int lrow = wid * 8 + rr;
        const int grow = row0 + lrow;
        const float4* r4 = (const float4*)(Ab + (size_t)grow * NN);
        float sum = 0.f;
#pragma unroll
        for (int w = 0; w < 8; w++) {
            float4 v = r4[w * 32 + lane];
            sum += v.x + v.y + v.z + v.w;
        }
#pragma unroll
        for (int off = 16; off > 0; off >>= 1)
            sum += __shfl_down_sync(0xFFFFFFFFu, sum, off);
        if (lane == 0) {
            float ad  = Ab[(size_t)grow * NN + grow];
            float deg = sum - ad + 1.0f;
            float inv = 1.0f / (EPS + deg);
            float sv  = 1.0f / (EPS + sqrtf(deg));
            g_s[b * NN + grow]  = sv;
            smf[(OFF_ADIAG >> 2) + lrow] = h2f_rn(ad);
            smf[(OFF_INV >> 2) + lrow]   = inv;
            smf[(OFF_SROW >> 2) + lrow]  = sv;
        }
    }
    grid_sync(0);

    // ============ PHASE 1.5: build g_Bh[b][f][k0..k0+128) (fp16, f-major) ====
    {
        float* xt = smf + (OFF_DYN >> 2);          // [128][65]
        float* sk = xt + 128 * 65;                 // [128]
        const int k0 = blockIdx.x * 128;
        const float* xs = x + ((size_t)b * NN + k0) * FDIM;
#pragma unroll
        for (int q = 0; q < 4; q++) {
            int e = tid + q * 512;
            int row = e >> 4, c4 = (e & 15) * 4;
            float4 v = *(const float4*)&xs[(size_t)row * FDIM + c4];
            xt[row * 65 + c4] = v.x;  xt[row * 65 + c4 + 1] = v.y;
            xt[row * 65 + c4 + 2] = v.z; xt[row * 65 + c4 + 3] = v.w;
        }
        if (tid < 128) sk[tid] = g_s[b * NN + k0 + tid];
        __syncthreads();
        uint32_t* dst = (uint32_t*)(g_Bh + (size_t)b * 128 * NN + k0);
#pragma unroll
        for (int q = 0; q < 16; q++) {
            int e = tid + q * 512;
            int f = e >> 6, kp = e & 63;
            float v0, v1;
            if (f < 64) {
                v0 = xt[(2 * kp) * 65 + f];
                v1 = xt[(2 * kp + 1) * 65 + f];
            } else {
                v0 = sk[2 * kp] * xt[(2 * kp) * 65 + f - 64];
                v1 = sk[2 * kp + 1] * xt[(2 * kp + 1) * 65 + f - 64];
            }
            dst[(size_t)f * (NN / 2) + kp] = h2pack(v0, v1);
        }
    }
    grid_sync(1);

    // ================= PHASE 2: warp-specialized fp16 GEMMs ==================
    if (wid >= 8) {
        // ------------- PRODUCER (leads consumers by one stage) -------------
        const int ptid = tid - 256;
        const int arow = ptid >> 3;              // 0..31 (+32q)
        const int acol = (ptid & 7) * 4;
        const int bf   = ptid >> 1;              // 0..127 (f row)
        const int bch  = (ptid & 1) * 2;
        const float* gA = Ab + (size_t)(row0 + arow) * NN + acol;
        const __half* gB = Bb + (size_t)bf * NN;

        float4 va[4];
        // prologue: stages 0,1; prefetch A(2)
#pragma unroll
        for (int st = 0; st < 2; st++) {
            const int k0 = st * KC;
#pragma unroll
            for (int q = 0; q < 4; q++)
                va[q] = *(const float4*)(gA + k0 + (size_t)q * 32 * NN);
            char* dA = smc + OFF_STAGE(st);
#pragma unroll
            for (int q = 0; q < 4; q++) {
                uint2 w;
                w.x = h2pack(va[q].x, va[q].y);
                w.y = h2pack(va[q].z, va[q].w);
                *(uint2*)(dA + (arow + 32 * q) * 80 + acol * 2) = w;
            }
            uint32_t sBb = sb + OFF_STAGE(st) + ASTG_B;
#pragma unroll
            for (int q = 0; q < 2; q++)
                cp_async16(sBb + (bf * 80 + (bch + q) * 16), gB + k0 + (bch + q) * 8);
            CP_COMMIT();
        }
#pragma unroll
        for (int q = 0; q < 4; q++)
            va[q] = *(const float4*)(gA + 2 * KC + (size_t)q * 32 * NN);
        CP_WAIT1();            // B(0) landed
        MEMBAR_CTA();
        bar_arrive512(1 + 0);  // full[0]

        // mainloop: at iter it fill stage it+2, publish full[it+1]
        for (int it = 0; it < NITER; ++it) {
            if (it + 2 < NITER) {
                const int s2 = (it + 2) % 3;
                if (it >= 1) bar_sync512(4 + s2);        // stage reuse gate
                char* dA = smc + OFF_STAGE(s2);
#pragma unroll
                for (int q = 0; q < 4; q++) {            // va = A(it+2)
                    uint2 w;
                    w.x = h2pack(va[q].x, va[q].y);
                    w.y = h2pack(va[q].z, va[q].w);
                    *(uint2*)(dA + (arow + 32 * q) * 80 + acol * 2) = w;
                }
                const int k0 = (it + 2) * KC;
                uint32_t sBb = sb + OFF_STAGE(s2) + ASTG_B;
#pragma unroll
                for (int q = 0; q < 2; q++)
                    cp_async16(sBb + (bf * 80 + (bch + q) * 16),
                               gB + k0 + (bch + q) * 8);
                CP_COMMIT();
                if (it + 3 < NITER) {
                    const int kn = (it + 3) * KC;
#pragma unroll
                    for (int q = 0; q < 4; q++)
                        va[q] = *(const float4*)(gA + kn + (size_t)q * 32 * NN);
                }
            }
            if (it + 1 < NITER) {
                if (it + 2 < NITER) { CP_WAIT1(); } else { CP_WAIT0(); }
                MEMBAR_CTA();
                bar_arrive512(1 + (it + 1) % 3);         // full[it+1]
            }
        }
        // stage KmatT fp16 [n:128][k:192] while consumers drain tail
        {
            uint32_t* km = (uint32_t*)(smc + OFF_KM);
#pragma unroll 1
            for (int e = ptid; e < 128 * 96; e += 256) {
                int n = e / 96;
                int kp = e - n * 96;
                float v0 = __ldg(&Kmat[(size_t)(2 * kp) * 128 + n]);
                float v1 = __ldg(&Kmat[(size_t)(2 * kp + 1) * 128 + n]);
                km[n * KM_STRH + kp] = h2pack(v0, v1);
            }
        }
    } else {
        // ---------------- CONSUMER ----------------
        const int m_base = (wid >> 2) * 64;
        const int n_base = (wid & 3) * 32;
        const bool scaled = (n_base >= 64);
        const int f_base = scaled ? n_base - 64 : n_base;

        float acc[4][4][4];
#pragma unroll
        for (int mt = 0; mt < 4; mt++)
#pragma unroll
            for (int nt = 0; nt < 4; nt++)
#pragma unroll
                for (int q = 0; q < 4; q++) acc[mt][nt][q] = 0.f;

        for (int it = 0; it < NITER; ++it) {
            const int s = it % 3;
            bar_sync512(1 + s);
            const uint32_t* sA = (const uint32_t*)(smc + OFF_STAGE(s));
            const uint32_t* sB = (const uint32_t*)(smc + OFF_STAGE(s) + ASTG_B);
#pragma unroll
            for (int ks = 0; ks < 2; ks++) {
                const int kb = ks * 8;
                uint32_t af[4][4], bf2[4][2];
#pragma unroll
                for (int mt = 0; mt < 4; mt++) {
                    const uint32_t* p = sA + (m_base + mt * 16 + lr) * SA_STRH + kb + lc;
                    af[mt][0] = p[0];
                    af[mt][1] = p[8 * SA_STRH];
                    af[mt][2] = p[4];
                    af[mt][3] = p[8 * SA_STRH + 4];
                }
#pragma unroll
                for (int nt = 0; nt < 4; nt++) {
                    const uint32_t* p = sB + (n_base + nt * 8 + lr) * SA_STRH + kb + lc;
                    bf2[nt][0] = p[0];
                    bf2[nt][1] = p[4];
                }
#pragma unroll
                for (int mt = 0; mt < 4; mt++)
#pragma unroll
                    for (int nt = 0; nt < 4; nt++)
                        mma_f16(acc[mt][nt], af[mt], bf2[nt]);
            }
            bar_arrive512(4 + s);
        }
        bar_sync_n(7, 256);

        // epilogue 1 -> ocat fp16 [128][192]
        uint32_t* oc = (uint32_t*)(smc + OFF_OC);
#pragma unroll
        for (int mt = 0; mt < 4; mt++) {
#pragma unroll
            for (int nt = 0; nt < 4; nt++) {
                const int f = f_base + nt * 8 + lc * 2;
#pragma unroll
                for (int h = 0; h < 2; h++) {
                    const int r = m_base + mt * 16 + lr + h * 8;
                    const float ad = smf[(OFF_ADIAG >> 2) + r];
                    const float c0 = acc[mt][nt][h * 2 + 0];
                    const float c1 = acc[mt][nt][h * 2 + 1];
                    float2 xv = *(const float2*)&xb[(size_t)(row0 + r) * FDIM + f];
                    if (!scaled) {
                        const float inv = smf[(OFF_INV >> 2) + r];
                        float xhx = h2f_rn(xv.x), xhy = h2f_rn(xv.y);
                        float o1a = c0 - ad * xhx;
                        float o1b = c1 - ad * xhy;
                        oc[r * OC_STRH + (f >> 1)] = h2pack(o1a, o1b);
                        oc[r * OC_STRH + ((64 + f) >> 1)] =
                            h2pack(inv * (o1a + xv.x), inv * (o1b + xv.y));
                    } else {
                        const float sv = smf[(OFF_SROW >> 2) + r];
                        float sxx = h2f_rn(sv * xv.x), sxy = h2f_rn(sv * xv.y);
                        float o3a = sv * c0 - sv * ad * sxx + sv * sv * xv.x;
                        float o3b = sv * c1 - sv * ad * sxy + sv * sv * xv.y;
                        oc[r * OC_STRH + ((128 + f) >> 1)] = h2pack(o3a, o3b);
                    }
                }
            }
        }
    }
    __syncthreads();

    // ---- GEMM2: out[128,128] = ocat[128,192] @ KmatT^T  (fp16, 12 k-steps)
    const int mm = (wid >> 2) * 32;
    const int n4 = (wid & 3) * 32;
    const uint32_t* ocp = (const uint32_t*)(smc + OFF_OC);
    const uint32_t* kmp = (const uint32_t*)(smc + OFF_KM);
    float acc2[2][4][4];
#pragma unroll
    for (int mt = 0; mt < 2; mt++)
#pragma unroll
        for (int nt = 0; nt < 4; nt++)
#pragma unroll
            for (int q = 0; q < 4; q++) acc2[mt][nt][q] = 0.f;

#pragma unroll
    for (int ks = 0; ks < 12; ks++) {
        const int kb = ks * 8;
        uint32_t af[2][4], bf2[4][2];
#pragma unroll
        for (int mt = 0; mt < 2; mt++) {
            const uint32_t* p = ocp + (mm + mt * 16 + lr) * OC_STRH + kb + lc;
            af[mt][0] = p[0];
            af[mt][1] = p[8 * OC_STRH];
            af[mt][2] = p[4];
            af[mt][3] = p[8 * OC_STRH + 4];
        }
#pragma unroll
        for (int nt = 0; nt < 4; nt++) {
            const uint32_t* p = kmp + (n4 + nt * 8 + lr) * KM_STRH + kb + lc;
            bf2[nt][0] = p[0];
            bf2[nt][1] = p[4];
        }
#pragma unroll
        for (int mt = 0; mt < 2; mt++)
#pragma unroll
            for (int nt = 0; nt < 4; nt++)
                mma_f16(acc2[mt][nt], af[mt], bf2[nt]);
    }

    // ---- bias + relu + store
#pragma unroll
    for (int mt = 0; mt < 2; mt++) {
#pragma unroll
        for (int nt = 0; nt < 4; nt++) {
            const int col = n4 + nt * 8 + lc * 2;
            float2 bv = *(const float2*)&bias[col];
#pragma unroll
            for (int h = 0; h < 2; h++) {
                const int r = mm + mt * 16 + lr + h * 8;
                float2 o;
                o.x = fmaxf(acc2[mt][nt][h * 2 + 0] + bv.x, 0.f);
                o.y = fmaxf(acc2[mt][nt][h * 2 + 1] + bv.y, 0.f);
                *(float2*)&out[((size_t)b * NN + row0 + r) * OUTD + col] = o;
            }
        }
    }
}

// ---------------------------------------------------------------------------
extern "C" void kernel_launch(void* const* d_in, const int* in_sizes, int n_in,
                              void* d_out, int out_size) {
    const float *x = nullptr, *A = nullptr, *Kmat = nullptr, *bias = nullptr;
    for (int i = 0; i < n_in; i++) {
        switch (in_sizes[i]) {
            case B_ * NN * FDIM:  x    = (const float*)d_in[i]; break;
            case B_ * NN * NN:    A    = (const float*)d_in[i]; break;
            case 3 * FDIM * OUTD: Kmat = (const float*)d_in[i]; break;
            case OUTD:            bias = (const float*)d_in[i]; break;
        }
    }
    float* out = (float*)d_out;

    static bool attr_set = false;
    if (!attr_set) {
        cudaFuncSetAttribute(mega_kernel,
                             cudaFuncAttributeMaxDynamicSharedMemorySize, SMEM_BYTES);
        attr_set = true;
    }

    reset_kernel<<<1, 1>>>();
    mega_kernel<<<dim3(NN / 128, B_), 512, SMEM_BYTES>>>(A, x, Kmat, bias, out);
}